// round 1
// baseline (speedup 1.0000x reference)
#include <cuda_runtime.h>
#include <cuda_bf16.h>
#include <cstdint>

#define BHN 16
#define SEQ 4096
#define HD 64
#define BM 128
#define BN 64
#define NTHREADS 256
#define KPITCH 72   // smem row pitch in bf16 elems (padding vs bank conflicts)

__device__ __forceinline__ float ex2f(float x) {
    float y;
    asm("ex2.approx.f32 %0, %1;" : "=f"(y) : "f"(x));
    return y;
}

__device__ __forceinline__ uint32_t packbf(float a, float b) {
    __nv_bfloat162 t;
    t.x = __float2bfloat16(a);
    t.y = __float2bfloat16(b);
    return reinterpret_cast<uint32_t&>(t);
}

// split a,b into bf16 hi pair and bf16 residual-lo pair
__device__ __forceinline__ void split2(float a, float b, uint32_t& hi, uint32_t& lo) {
    __nv_bfloat16 ha = __float2bfloat16(a), hb = __float2bfloat16(b);
    __nv_bfloat162 hh; hh.x = ha; hh.y = hb;
    hi = reinterpret_cast<uint32_t&>(hh);
    __nv_bfloat162 ll;
    ll.x = __float2bfloat16(a - __bfloat162float(ha));
    ll.y = __float2bfloat16(b - __bfloat162float(hb));
    lo = reinterpret_cast<uint32_t&>(ll);
}

__device__ __forceinline__ void mma16816(float c[4], const uint32_t a[4],
                                         uint32_t b0, uint32_t b1) {
    asm volatile(
        "mma.sync.aligned.m16n8k16.row.col.f32.bf16.bf16.f32 "
        "{%0,%1,%2,%3},{%4,%5,%6,%7},{%8,%9},{%0,%1,%2,%3};"
        : "+f"(c[0]), "+f"(c[1]), "+f"(c[2]), "+f"(c[3])
        : "r"(a[0]), "r"(a[1]), "r"(a[2]), "r"(a[3]), "r"(b0), "r"(b1));
}

// load a [BN x HD] fp32 tile, convert to bf16 hi (and optional lo) into padded smem
template <bool WANT_LO>
__device__ __forceinline__ void load_tile_split(const float* __restrict__ src, int kt,
                                                __nv_bfloat16* hi, __nv_bfloat16* lo,
                                                int tid) {
    const float4* s = reinterpret_cast<const float4*>(src + (size_t)kt * BN * HD);
#pragma unroll
    for (int it = 0; it < (BN * HD / 4) / NTHREADS; ++it) {
        int i = tid + it * NTHREADS;
        float4 f = s[i];
        int r = i >> 4;          // row (key)
        int c = (i & 15) << 2;   // col (d)
        int base = r * KPITCH + c;
        __nv_bfloat16 h0 = __float2bfloat16(f.x);
        __nv_bfloat16 h1 = __float2bfloat16(f.y);
        __nv_bfloat16 h2 = __float2bfloat16(f.z);
        __nv_bfloat16 h3 = __float2bfloat16(f.w);
        hi[base + 0] = h0; hi[base + 1] = h1; hi[base + 2] = h2; hi[base + 3] = h3;
        if (WANT_LO) {
            lo[base + 0] = __float2bfloat16(f.x - __bfloat162float(h0));
            lo[base + 1] = __float2bfloat16(f.y - __bfloat162float(h1));
            lo[base + 2] = __float2bfloat16(f.z - __bfloat162float(h2));
            lo[base + 3] = __float2bfloat16(f.w - __bfloat162float(h3));
        }
    }
}

// pack two bf16 from rows k and k+1 (same d) of a [key][d] smem tile
__device__ __forceinline__ uint32_t ld2k(const __nv_bfloat16* base, int k, int d) {
    uint32_t l = *reinterpret_cast<const uint16_t*>(base + k * KPITCH + d);
    uint32_t h = *reinterpret_cast<const uint16_t*>(base + (k + 1) * KPITCH + d);
    return l | (h << 16);
}

__global__ void __launch_bounds__(NTHREADS)
attn_kernel(const float* __restrict__ Qg, const float* __restrict__ Kg,
            const float* __restrict__ Vg, float* __restrict__ out) {
    __shared__ __nv_bfloat16 Kh[BN * KPITCH];
    __shared__ __nv_bfloat16 Kl[BN * KPITCH];
    __shared__ __nv_bfloat16 Vh[BN * KPITCH];
    __shared__ __nv_bfloat16 Vl[BN * KPITCH];

    const int bh = blockIdx.y;
    const float* Qb = Qg + (size_t)bh * SEQ * HD;
    const float* Kb = Kg + (size_t)bh * SEQ * HD;
    const float* Vb = Vg + (size_t)bh * SEQ * HD;
    float* Ob = out + (size_t)bh * SEQ * HD;
    float* Ab = out + (size_t)BHN * SEQ * HD + (size_t)bh * SEQ * SEQ;

    const int tid = threadIdx.x;
    const int warp = tid >> 5;
    const int lane = tid & 31;
    const int g = lane >> 2;   // group (row within 8)
    const int qq = lane & 3;   // quad index
    const int row0 = blockIdx.x * BM + warp * 16;

    // ---- load Q fragments (persist in regs): hi and lo splits, 4 k-chunks ----
    uint32_t qh[4][4], ql[4][4];
#pragma unroll
    for (int kc = 0; kc < 4; ++kc) {
#pragma unroll
        for (int p = 0; p < 4; ++p) {
            int r = row0 + g + (p & 1) * 8;
            int d = kc * 16 + (p >> 1) * 8 + qq * 2;
            float2 f = *reinterpret_cast<const float2*>(Qb + (size_t)r * HD + d);
            split2(f.x, f.y, qh[kc][p], ql[kc][p]);
        }
    }

    const float SC = 0.1803368801111244f;  // (1/sqrt(64)) * log2(e)

    // ================= PASS A: row sums (hi*hi only) =================
    float rs0 = 0.f, rs1 = 0.f;
    for (int kt = 0; kt < SEQ / BN; ++kt) {
        __syncthreads();
        load_tile_split<false>(Kb, kt, Kh, nullptr, tid);
        __syncthreads();
        float c[8][4] = {};
#pragma unroll
        for (int kc = 0; kc < 4; ++kc) {
#pragma unroll
            for (int nt = 0; nt < 8; ++nt) {
                const __nv_bfloat16* kp = Kh + (nt * 8 + g) * KPITCH + kc * 16 + qq * 2;
                uint32_t b0 = *reinterpret_cast<const uint32_t*>(kp);
                uint32_t b1 = *reinterpret_cast<const uint32_t*>(kp + 8);
                mma16816(c[nt], qh[kc], b0, b1);
            }
        }
#pragma unroll
        for (int nt = 0; nt < 8; ++nt) {
            rs0 += ex2f(c[nt][0] * SC) + ex2f(c[nt][1] * SC);
            rs1 += ex2f(c[nt][2] * SC) + ex2f(c[nt][3] * SC);
        }
    }
    rs0 += __shfl_xor_sync(0xffffffffu, rs0, 1);
    rs0 += __shfl_xor_sync(0xffffffffu, rs0, 2);
    rs1 += __shfl_xor_sync(0xffffffffu, rs1, 1);
    rs1 += __shfl_xor_sync(0xffffffffu, rs1, 2);
    const float inv0 = 1.f / rs0;
    const float inv1 = 1.f / rs1;

    // ================= PASS B: precise S, write attention, accumulate O ============
    float o[8][4] = {};
    for (int kt = 0; kt < SEQ / BN; ++kt) {
        __syncthreads();
        load_tile_split<true>(Kb, kt, Kh, Kl, tid);
        load_tile_split<true>(Vb, kt, Vh, Vl, tid);
        __syncthreads();

        float c[8][4] = {};
#pragma unroll
        for (int kc = 0; kc < 4; ++kc) {
#pragma unroll
            for (int nt = 0; nt < 8; ++nt) {
                const __nv_bfloat16* kph = Kh + (nt * 8 + g) * KPITCH + kc * 16 + qq * 2;
                const __nv_bfloat16* kpl = Kl + (nt * 8 + g) * KPITCH + kc * 16 + qq * 2;
                uint32_t bh0 = *reinterpret_cast<const uint32_t*>(kph);
                uint32_t bh1 = *reinterpret_cast<const uint32_t*>(kph + 8);
                uint32_t bl0 = *reinterpret_cast<const uint32_t*>(kpl);
                uint32_t bl1 = *reinterpret_cast<const uint32_t*>(kpl + 8);
                mma16816(c[nt], qh[kc], bh0, bh1);   // hi*hi
                mma16816(c[nt], qh[kc], bl0, bl1);   // hi*lo
                mma16816(c[nt], ql[kc], bh0, bh1);   // lo*hi
            }
        }

        // exp + normalize + stream attention tile
#pragma unroll
        for (int nt = 0; nt < 8; ++nt) {
            c[nt][0] = ex2f(c[nt][0] * SC) * inv0;
            c[nt][1] = ex2f(c[nt][1] * SC) * inv0;
            c[nt][2] = ex2f(c[nt][2] * SC) * inv1;
            c[nt][3] = ex2f(c[nt][3] * SC) * inv1;
            size_t col = (size_t)kt * BN + nt * 8 + qq * 2;
            *reinterpret_cast<float2*>(Ab + (size_t)(row0 + g) * SEQ + col) =
                make_float2(c[nt][0], c[nt][1]);
            *reinterpret_cast<float2*>(Ab + (size_t)(row0 + g + 8) * SEQ + col) =
                make_float2(c[nt][2], c[nt][3]);
        }

        // AV: reuse C-layout as A-fragments, contract over the 64 keys of this tile
#pragma unroll
        for (int kcp = 0; kcp < 4; ++kcp) {
            const int t0 = 2 * kcp, t1 = 2 * kcp + 1;
            uint32_t ah[4], al[4];
            split2(c[t0][0], c[t0][1], ah[0], al[0]);
            split2(c[t0][2], c[t0][3], ah[1], al[1]);
            split2(c[t1][0], c[t1][1], ah[2], al[2]);
            split2(c[t1][2], c[t1][3], ah[3], al[3]);
            const int k0 = kcp * 16 + qq * 2;
#pragma unroll
            for (int nt = 0; nt < 8; ++nt) {
                const int d = nt * 8 + g;
                uint32_t vh0 = ld2k(Vh, k0, d);
                uint32_t vh1 = ld2k(Vh, k0 + 8, d);
                uint32_t vl0 = ld2k(Vl, k0, d);
                uint32_t vl1 = ld2k(Vl, k0 + 8, d);
                mma16816(o[nt], ah, vh0, vh1);   // hi*hi
                mma16816(o[nt], ah, vl0, vl1);   // hi*lo
                mma16816(o[nt], al, vh0, vh1);   // lo*hi
            }
        }
    }

    // ---- write O ----
#pragma unroll
    for (int nt = 0; nt < 8; ++nt) {
        int col = nt * 8 + qq * 2;
        *reinterpret_cast<float2*>(Ob + (size_t)(row0 + g) * HD + col) =
            make_float2(o[nt][0], o[nt][1]);
        *reinterpret_cast<float2*>(Ob + (size_t)(row0 + g + 8) * HD + col) =
            make_float2(o[nt][2], o[nt][3]);
    }
}

extern "C" void kernel_launch(void* const* d_in, const int* in_sizes, int n_in,
                              void* d_out, int out_size) {
    const float* q = (const float*)d_in[0];
    const float* k = (const float*)d_in[1];
    const float* v = (const float*)d_in[2];
    (void)in_sizes; (void)n_in; (void)out_size;
    dim3 grid(SEQ / BM, BHN);
    attn_kernel<<<grid, NTHREADS>>>(q, k, v, (float*)d_out);
}

// round 2
// speedup vs baseline: 1.1980x; 1.1980x over previous
#include <cuda_runtime.h>
#include <cuda_bf16.h>
#include <cstdint>

#define BHN 16
#define SEQ 4096
#define HD 64
#define BM 128
#define BN 64
#define NTHREADS 256
#define KPITCH 72   // smem row pitch in bf16 elems (144B rows -> conflict-free LDSM)

__device__ __forceinline__ float ex2f(float x) {
    float y;
    asm("ex2.approx.f32 %0, %1;" : "=f"(y) : "f"(x));
    return y;
}

// split a,b into bf16 hi pair and bf16 residual-lo pair
__device__ __forceinline__ void split2(float a, float b, uint32_t& hi, uint32_t& lo) {
    __nv_bfloat16 ha = __float2bfloat16(a), hb = __float2bfloat16(b);
    __nv_bfloat162 hh; hh.x = ha; hh.y = hb;
    hi = reinterpret_cast<uint32_t&>(hh);
    __nv_bfloat162 ll;
    ll.x = __float2bfloat16(a - __bfloat162float(ha));
    ll.y = __float2bfloat16(b - __bfloat162float(hb));
    lo = reinterpret_cast<uint32_t&>(ll);
}

__device__ __forceinline__ uint32_t packbf(float a, float b) {
    __nv_bfloat162 t; t.x = __float2bfloat16(a); t.y = __float2bfloat16(b);
    return reinterpret_cast<uint32_t&>(t);
}

__device__ __forceinline__ void mma16816(float c[4], const uint32_t a[4],
                                         uint32_t b0, uint32_t b1) {
    asm volatile(
        "mma.sync.aligned.m16n8k16.row.col.f32.bf16.bf16.f32 "
        "{%0,%1,%2,%3},{%4,%5,%6,%7},{%8,%9},{%0,%1,%2,%3};"
        : "+f"(c[0]), "+f"(c[1]), "+f"(c[2]), "+f"(c[3])
        : "r"(a[0]), "r"(a[1]), "r"(a[2]), "r"(a[3]), "r"(b0), "r"(b1));
}

__device__ __forceinline__ void ldsm_x4(uint32_t& r0, uint32_t& r1, uint32_t& r2,
                                        uint32_t& r3, uint32_t addr) {
    asm volatile("ldmatrix.sync.aligned.m8n8.x4.shared.b16 {%0,%1,%2,%3},[%4];"
                 : "=r"(r0), "=r"(r1), "=r"(r2), "=r"(r3) : "r"(addr));
}

__device__ __forceinline__ void ldsm_x4_t(uint32_t& r0, uint32_t& r1, uint32_t& r2,
                                          uint32_t& r3, uint32_t addr) {
    asm volatile("ldmatrix.sync.aligned.m8n8.x4.trans.shared.b16 {%0,%1,%2,%3},[%4];"
                 : "=r"(r0), "=r"(r1), "=r"(r2), "=r"(r3) : "r"(addr));
}

// load a [BN x HD] fp32 tile, convert to bf16 hi (and optional lo), packed STS.64
template <bool WANT_LO>
__device__ __forceinline__ void load_tile_split(const float* __restrict__ src, int kt,
                                                __nv_bfloat16* hi, __nv_bfloat16* lo,
                                                int tid) {
    const float4* s = reinterpret_cast<const float4*>(src + (size_t)kt * BN * HD);
#pragma unroll
    for (int it = 0; it < (BN * HD / 4) / NTHREADS; ++it) {
        int i = tid + it * NTHREADS;
        float4 f = s[i];
        int r = i >> 4;          // row (key)
        int c = (i & 15) << 2;   // col (d)
        int base = r * KPITCH + c;
        __nv_bfloat16 h0 = __float2bfloat16(f.x);
        __nv_bfloat16 h1 = __float2bfloat16(f.y);
        __nv_bfloat16 h2 = __float2bfloat16(f.z);
        __nv_bfloat16 h3 = __float2bfloat16(f.w);
        uint2 hp;
        hp.x = (uint32_t)*reinterpret_cast<uint16_t*>(&h0) |
               ((uint32_t)*reinterpret_cast<uint16_t*>(&h1) << 16);
        hp.y = (uint32_t)*reinterpret_cast<uint16_t*>(&h2) |
               ((uint32_t)*reinterpret_cast<uint16_t*>(&h3) << 16);
        *reinterpret_cast<uint2*>(hi + base) = hp;
        if (WANT_LO) {
            uint2 lp;
            lp.x = packbf(f.x - __bfloat162float(h0), f.y - __bfloat162float(h1));
            lp.y = packbf(f.z - __bfloat162float(h2), f.w - __bfloat162float(h3));
            *reinterpret_cast<uint2*>(lo + base) = lp;
        }
    }
}

__global__ void __launch_bounds__(NTHREADS, 2)
attn_kernel(const float* __restrict__ Qg, const float* __restrict__ Kg,
            const float* __restrict__ Vg, float* __restrict__ out) {
    __shared__ __nv_bfloat16 Kh[BN * KPITCH];
    __shared__ __nv_bfloat16 Kl[BN * KPITCH];
    __shared__ __nv_bfloat16 Vh[BN * KPITCH];
    __shared__ __nv_bfloat16 Vl[BN * KPITCH];

    const int bh = blockIdx.y;
    const float* Qb = Qg + (size_t)bh * SEQ * HD;
    const float* Kb = Kg + (size_t)bh * SEQ * HD;
    const float* Vb = Vg + (size_t)bh * SEQ * HD;
    float* Ob = out + (size_t)bh * SEQ * HD;
    float* Ab = out + (size_t)BHN * SEQ * HD + (size_t)bh * SEQ * SEQ;

    const int tid = threadIdx.x;
    const int warp = tid >> 5;
    const int lane = tid & 31;
    const int g = lane >> 2;   // group (row within 8)
    const int qq = lane & 3;   // quad index
    const int row0 = blockIdx.x * BM + warp * 16;

    // ---- LDSM lane-invariant base addresses ----
    // QK (non-trans): lane -> row r = (l&7) + ((l&16)?8:0), col8 = (l&8)?8:0
    const int qk_r = (lane & 7) + ((lane & 16) ? 8 : 0);
    const int qk_c = (lane & 8) ? 8 : 0;
    const uint32_t aKh = (uint32_t)__cvta_generic_to_shared(Kh) +
                         (uint32_t)((qk_r * KPITCH + qk_c) * 2);
    const uint32_t aKl = (uint32_t)__cvta_generic_to_shared(Kl) +
                         (uint32_t)((qk_r * KPITCH + qk_c) * 2);
    // V (trans): lane -> row r = (l&7) + ((l&8)?8:0), col8 = (l&16)?8:0
    const int v_r = (lane & 7) + ((lane & 8) ? 8 : 0);
    const int v_c = (lane & 16) ? 8 : 0;
    const uint32_t aVh = (uint32_t)__cvta_generic_to_shared(Vh) +
                         (uint32_t)((v_r * KPITCH + v_c) * 2);
    const uint32_t aVl = (uint32_t)__cvta_generic_to_shared(Vl) +
                         (uint32_t)((v_r * KPITCH + v_c) * 2);
    const uint32_t NPOFF = 16 * KPITCH * 2;  // 16 rows step (bytes)

    // ---- load Q fragments (persist in regs): hi and lo splits, 4 k-chunks ----
    uint32_t qh[4][4], ql[4][4];
#pragma unroll
    for (int kc = 0; kc < 4; ++kc) {
#pragma unroll
        for (int p = 0; p < 4; ++p) {
            int r = row0 + g + (p & 1) * 8;
            int d = kc * 16 + (p >> 1) * 8 + qq * 2;
            float2 f = *reinterpret_cast<const float2*>(Qb + (size_t)r * HD + d);
            split2(f.x, f.y, qh[kc][p], ql[kc][p]);
        }
    }

    const float SC = 0.1803368801111244f;  // (1/sqrt(64)) * log2(e)

    // ================= PASS A: row sums (hi*hi only) =================
    float rs0 = 0.f, rs1 = 0.f;
    for (int kt = 0; kt < SEQ / BN; ++kt) {
        __syncthreads();
        load_tile_split<false>(Kb, kt, Kh, nullptr, tid);
        __syncthreads();
        float c[8][4] = {};
#pragma unroll
        for (int kc = 0; kc < 4; ++kc) {
#pragma unroll
            for (int np = 0; np < 4; ++np) {
                uint32_t h0, h1, h2, h3;
                ldsm_x4(h0, h1, h2, h3, aKh + np * NPOFF + kc * 32);
                mma16816(c[2 * np], qh[kc], h0, h1);
                mma16816(c[2 * np + 1], qh[kc], h2, h3);
            }
        }
#pragma unroll
        for (int nt = 0; nt < 8; ++nt) {
            rs0 += ex2f(c[nt][0] * SC) + ex2f(c[nt][1] * SC);
            rs1 += ex2f(c[nt][2] * SC) + ex2f(c[nt][3] * SC);
        }
    }
    rs0 += __shfl_xor_sync(0xffffffffu, rs0, 1);
    rs0 += __shfl_xor_sync(0xffffffffu, rs0, 2);
    rs1 += __shfl_xor_sync(0xffffffffu, rs1, 1);
    rs1 += __shfl_xor_sync(0xffffffffu, rs1, 2);
    const float inv0 = 1.f / rs0;
    const float inv1 = 1.f / rs1;

    // ========== PASS B: precise S, write attention, accumulate O ==========
    float o[8][4] = {};
    for (int kt = 0; kt < SEQ / BN; ++kt) {
        __syncthreads();
        load_tile_split<true>(Kb, kt, Kh, Kl, tid);
        load_tile_split<true>(Vb, kt, Vh, Vl, tid);
        __syncthreads();

        float c[8][4] = {};
#pragma unroll
        for (int kc = 0; kc < 4; ++kc) {
#pragma unroll
            for (int np = 0; np < 4; ++np) {
                uint32_t h0, h1, h2, h3, l0, l1, l2, l3;
                ldsm_x4(h0, h1, h2, h3, aKh + np * NPOFF + kc * 32);
                ldsm_x4(l0, l1, l2, l3, aKl + np * NPOFF + kc * 32);
                mma16816(c[2 * np], qh[kc], h0, h1);       // hi*hi
                mma16816(c[2 * np], qh[kc], l0, l1);       // hi*lo
                mma16816(c[2 * np], ql[kc], h0, h1);       // lo*hi
                mma16816(c[2 * np + 1], qh[kc], h2, h3);
                mma16816(c[2 * np + 1], qh[kc], l2, l3);
                mma16816(c[2 * np + 1], ql[kc], h2, h3);
            }
        }

        // exp + normalize + stream attention tile (write-once: streaming hint)
#pragma unroll
        for (int nt = 0; nt < 8; ++nt) {
            c[nt][0] = ex2f(c[nt][0] * SC) * inv0;
            c[nt][1] = ex2f(c[nt][1] * SC) * inv0;
            c[nt][2] = ex2f(c[nt][2] * SC) * inv1;
            c[nt][3] = ex2f(c[nt][3] * SC) * inv1;
            size_t col = (size_t)kt * BN + nt * 8 + qq * 2;
            __stcs(reinterpret_cast<float2*>(Ab + (size_t)(row0 + g) * SEQ + col),
                   make_float2(c[nt][0], c[nt][1]));
            __stcs(reinterpret_cast<float2*>(Ab + (size_t)(row0 + g + 8) * SEQ + col),
                   make_float2(c[nt][2], c[nt][3]));
        }

        // AV: reuse C-layout as A-fragments, contract over the 64 keys of this tile
#pragma unroll
        for (int kcp = 0; kcp < 4; ++kcp) {
            const int t0 = 2 * kcp, t1 = 2 * kcp + 1;
            uint32_t ah[4], al[4];
            split2(c[t0][0], c[t0][1], ah[0], al[0]);
            split2(c[t0][2], c[t0][3], ah[1], al[1]);
            split2(c[t1][0], c[t1][1], ah[2], al[2]);
            split2(c[t1][2], c[t1][3], ah[3], al[3]);
#pragma unroll
            for (int np = 0; np < 4; ++np) {
                uint32_t vh0, vh1, vh2, vh3, vl0, vl1, vl2, vl3;
                ldsm_x4_t(vh0, vh1, vh2, vh3, aVh + kcp * NPOFF + np * 32);
                ldsm_x4_t(vl0, vl1, vl2, vl3, aVl + kcp * NPOFF + np * 32);
                mma16816(o[2 * np], ah, vh0, vh1);        // hi*hi
                mma16816(o[2 * np], ah, vl0, vl1);        // hi*lo
                mma16816(o[2 * np], al, vh0, vh1);        // lo*hi
                mma16816(o[2 * np + 1], ah, vh2, vh3);
                mma16816(o[2 * np + 1], ah, vl2, vl3);
                mma16816(o[2 * np + 1], al, vh2, vh3);
            }
        }
    }

    // ---- write O ----
#pragma unroll
    for (int nt = 0; nt < 8; ++nt) {
        int col = nt * 8 + qq * 2;
        *reinterpret_cast<float2*>(Ob + (size_t)(row0 + g) * HD + col) =
            make_float2(o[nt][0], o[nt][1]);
        *reinterpret_cast<float2*>(Ob + (size_t)(row0 + g + 8) * HD + col) =
            make_float2(o[nt][2], o[nt][3]);
    }
}

extern "C" void kernel_launch(void* const* d_in, const int* in_sizes, int n_in,
                              void* d_out, int out_size) {
    const float* q = (const float*)d_in[0];
    const float* k = (const float*)d_in[1];
    const float* v = (const float*)d_in[2];
    (void)in_sizes; (void)n_in; (void)out_size;
    dim3 grid(SEQ / BM, BHN);
    attn_kernel<<<grid, NTHREADS>>>(q, k, v, (float*)d_out);
}

// round 3
// speedup vs baseline: 2.0081x; 1.6762x over previous
#include <cuda_runtime.h>
#include <cuda_fp16.h>
#include <cstdint>

#define BHN 16
#define SEQ 4096
#define HD 64
#define BM 128
#define BN 64
#define NTHREADS 256
#define KPITCH 72   // smem row pitch in halves (144B rows -> conflict-free LDSM)
#define NT (SEQ / BN)

// fp16 scratch copies of K and V (converted once per launch)
__device__ __half2 Ksc[BHN * SEQ * HD / 2];
__device__ __half2 Vsc[BHN * SEQ * HD / 2];

__device__ __forceinline__ float ex2f(float x) {
    float y;
    asm("ex2.approx.f32 %0, %1;" : "=f"(y) : "f"(x));
    return y;
}

__device__ __forceinline__ uint32_t packh2(float a, float b) {
    __half2 t = __floats2half2_rn(a, b);
    return reinterpret_cast<uint32_t&>(t);
}

__device__ __forceinline__ void mma16816(float c[4], const uint32_t a[4],
                                         uint32_t b0, uint32_t b1) {
    asm volatile(
        "mma.sync.aligned.m16n8k16.row.col.f32.f16.f16.f32 "
        "{%0,%1,%2,%3},{%4,%5,%6,%7},{%8,%9},{%0,%1,%2,%3};"
        : "+f"(c[0]), "+f"(c[1]), "+f"(c[2]), "+f"(c[3])
        : "r"(a[0]), "r"(a[1]), "r"(a[2]), "r"(a[3]), "r"(b0), "r"(b1));
}

__device__ __forceinline__ void ldsm_x4(uint32_t& r0, uint32_t& r1, uint32_t& r2,
                                        uint32_t& r3, uint32_t addr) {
    asm volatile("ldmatrix.sync.aligned.m8n8.x4.shared.b16 {%0,%1,%2,%3},[%4];"
                 : "=r"(r0), "=r"(r1), "=r"(r2), "=r"(r3) : "r"(addr));
}

__device__ __forceinline__ void ldsm_x4_t(uint32_t& r0, uint32_t& r1, uint32_t& r2,
                                          uint32_t& r3, uint32_t addr) {
    asm volatile("ldmatrix.sync.aligned.m8n8.x4.trans.shared.b16 {%0,%1,%2,%3},[%4];"
                 : "=r"(r0), "=r"(r1), "=r"(r2), "=r"(r3) : "r"(addr));
}

__device__ __forceinline__ void cpasync16(uint32_t dst, const void* src) {
    asm volatile("cp.async.cg.shared.global [%0],[%1],16;" :: "r"(dst), "l"(src));
}
__device__ __forceinline__ void cp_commit() {
    asm volatile("cp.async.commit_group;");
}
template <int N>
__device__ __forceinline__ void cp_wait() {
    asm volatile("cp.async.wait_group %0;" :: "n"(N));
}

// prefetch one [BN x HD] fp16 tile into padded smem via cp.async (2 chunks/thread)
__device__ __forceinline__ void prefetch_tile(uint32_t dstbase, const __half* src,
                                              int tid) {
#pragma unroll
    for (int t = 0; t < 2; ++t) {
        int i = tid + t * NTHREADS;
        int r = i >> 3;
        int c = (i & 7) << 3;
        cpasync16(dstbase + (uint32_t)((r * KPITCH + c) * 2), src + r * HD + c);
    }
}

// ---------------- pre-conversion kernel ----------------
__global__ void __launch_bounds__(256)
convert_kernel(const float* __restrict__ K, const float* __restrict__ V) {
    const int n4 = BHN * SEQ * HD / 4;
    int i = blockIdx.x * blockDim.x + threadIdx.x;
    if (i < n4) {
        float4 f = reinterpret_cast<const float4*>(K)[i];
        Ksc[2 * i] = __floats2half2_rn(f.x, f.y);
        Ksc[2 * i + 1] = __floats2half2_rn(f.z, f.w);
    } else {
        int j = i - n4;
        float4 f = reinterpret_cast<const float4*>(V)[j];
        Vsc[2 * j] = __floats2half2_rn(f.x, f.y);
        Vsc[2 * j + 1] = __floats2half2_rn(f.z, f.w);
    }
}

// ---------------- main attention kernel ----------------
__global__ void __launch_bounds__(NTHREADS, 2)
attn_kernel(const float* __restrict__ Qg, float* __restrict__ out) {
    __shared__ __half Kb[2][BN * KPITCH];
    __shared__ __half Vb[2][BN * KPITCH];

    const int bh = blockIdx.y;
    const float* Qb = Qg + (size_t)bh * SEQ * HD;
    const __half* Kb16 = reinterpret_cast<const __half*>(Ksc) + (size_t)bh * SEQ * HD;
    const __half* Vb16 = reinterpret_cast<const __half*>(Vsc) + (size_t)bh * SEQ * HD;
    float* Ob = out + (size_t)bh * SEQ * HD;
    float* Ab = out + (size_t)BHN * SEQ * HD + (size_t)bh * SEQ * SEQ;

    const int tid = threadIdx.x;
    const int warp = tid >> 5;
    const int lane = tid & 31;
    const int g = lane >> 2;
    const int qq = lane & 3;
    const int row0 = blockIdx.x * BM + warp * 16;

    const uint32_t bK0 = (uint32_t)__cvta_generic_to_shared(&Kb[0][0]);
    const uint32_t bK1 = (uint32_t)__cvta_generic_to_shared(&Kb[1][0]);
    const uint32_t bV0 = (uint32_t)__cvta_generic_to_shared(&Vb[0][0]);
    const uint32_t bV1 = (uint32_t)__cvta_generic_to_shared(&Vb[1][0]);

    // LDSM lane offsets
    const int qk_r = (lane & 7) + ((lane & 16) ? 8 : 0);
    const int qk_c = (lane & 8) ? 8 : 0;
    const uint32_t offK = (uint32_t)((qk_r * KPITCH + qk_c) * 2);
    const int v_r = (lane & 7) + ((lane & 8) ? 8 : 0);
    const int v_c = (lane & 16) ? 8 : 0;
    const uint32_t offV = (uint32_t)((v_r * KPITCH + v_c) * 2);
    const uint32_t NPOFF = 16 * KPITCH * 2;

    // ---- Q fragments in fp16 (persist in regs) ----
    uint32_t qh[4][4];
#pragma unroll
    for (int kc = 0; kc < 4; ++kc) {
#pragma unroll
        for (int p = 0; p < 4; ++p) {
            int r = row0 + g + (p & 1) * 8;
            int d = kc * 16 + (p >> 1) * 8 + qq * 2;
            float2 f = *reinterpret_cast<const float2*>(Qb + (size_t)r * HD + d);
            qh[kc][p] = packh2(f.x, f.y);
        }
    }

    const float SC = 0.1803368801111244f;  // (1/sqrt(64)) * log2(e)

    // ================= PASS A: row sums =================
    float rs0 = 0.f, rs1 = 0.f;
    prefetch_tile(bK0, Kb16, tid);
    cp_commit();
    for (int kt = 0; kt < NT; ++kt) {
        if (kt + 1 < NT) {
            prefetch_tile((kt & 1) ? bK0 : bK1, Kb16 + (size_t)(kt + 1) * BN * HD, tid);
            cp_commit();
            cp_wait<1>();
        } else {
            cp_wait<0>();
        }
        __syncthreads();
        const uint32_t aK = ((kt & 1) ? bK1 : bK0) + offK;
        float c[8][4] = {};
#pragma unroll
        for (int kc = 0; kc < 4; ++kc) {
#pragma unroll
            for (int np = 0; np < 4; ++np) {
                uint32_t h0, h1, h2, h3;
                ldsm_x4(h0, h1, h2, h3, aK + np * NPOFF + kc * 32);
                mma16816(c[2 * np], qh[kc], h0, h1);
                mma16816(c[2 * np + 1], qh[kc], h2, h3);
            }
        }
#pragma unroll
        for (int nt = 0; nt < 8; ++nt) {
            rs0 += ex2f(c[nt][0] * SC) + ex2f(c[nt][1] * SC);
            rs1 += ex2f(c[nt][2] * SC) + ex2f(c[nt][3] * SC);
        }
        __syncthreads();
    }
    rs0 += __shfl_xor_sync(0xffffffffu, rs0, 1);
    rs0 += __shfl_xor_sync(0xffffffffu, rs0, 2);
    rs1 += __shfl_xor_sync(0xffffffffu, rs1, 1);
    rs1 += __shfl_xor_sync(0xffffffffu, rs1, 2);
    const float inv0 = 1.f / rs0;
    const float inv1 = 1.f / rs1;

    // ========== PASS B: S, write attention, accumulate O ==========
    float o[8][4] = {};
    prefetch_tile(bK0, Kb16, tid);
    prefetch_tile(bV0, Vb16, tid);
    cp_commit();
    for (int kt = 0; kt < NT; ++kt) {
        if (kt + 1 < NT) {
            const uint32_t dK = (kt & 1) ? bK0 : bK1;
            const uint32_t dV = (kt & 1) ? bV0 : bV1;
            prefetch_tile(dK, Kb16 + (size_t)(kt + 1) * BN * HD, tid);
            prefetch_tile(dV, Vb16 + (size_t)(kt + 1) * BN * HD, tid);
            cp_commit();
            cp_wait<1>();
        } else {
            cp_wait<0>();
        }
        __syncthreads();
        const uint32_t aK = ((kt & 1) ? bK1 : bK0) + offK;
        const uint32_t aV = ((kt & 1) ? bV1 : bV0) + offV;

        float c[8][4] = {};
#pragma unroll
        for (int kc = 0; kc < 4; ++kc) {
#pragma unroll
            for (int np = 0; np < 4; ++np) {
                uint32_t h0, h1, h2, h3;
                ldsm_x4(h0, h1, h2, h3, aK + np * NPOFF + kc * 32);
                mma16816(c[2 * np], qh[kc], h0, h1);
                mma16816(c[2 * np + 1], qh[kc], h2, h3);
            }
        }

        // exp + normalize + stream attention tile
#pragma unroll
        for (int nt = 0; nt < 8; ++nt) {
            c[nt][0] = ex2f(c[nt][0] * SC) * inv0;
            c[nt][1] = ex2f(c[nt][1] * SC) * inv0;
            c[nt][2] = ex2f(c[nt][2] * SC) * inv1;
            c[nt][3] = ex2f(c[nt][3] * SC) * inv1;
            size_t col = (size_t)kt * BN + nt * 8 + qq * 2;
            __stcs(reinterpret_cast<float2*>(Ab + (size_t)(row0 + g) * SEQ + col),
                   make_float2(c[nt][0], c[nt][1]));
            __stcs(reinterpret_cast<float2*>(Ab + (size_t)(row0 + g + 8) * SEQ + col),
                   make_float2(c[nt][2], c[nt][3]));
        }

        // AV: P (fp16) x V (fp16), C-layout reuse
#pragma unroll
        for (int kcp = 0; kcp < 4; ++kcp) {
            const int t0 = 2 * kcp, t1 = 2 * kcp + 1;
            uint32_t ah[4];
            ah[0] = packh2(c[t0][0], c[t0][1]);
            ah[1] = packh2(c[t0][2], c[t0][3]);
            ah[2] = packh2(c[t1][0], c[t1][1]);
            ah[3] = packh2(c[t1][2], c[t1][3]);
#pragma unroll
            for (int np = 0; np < 4; ++np) {
                uint32_t v0, v1, v2, v3;
                ldsm_x4_t(v0, v1, v2, v3, aV + kcp * NPOFF + np * 32);
                mma16816(o[2 * np], ah, v0, v1);
                mma16816(o[2 * np + 1], ah, v2, v3);
            }
        }
        __syncthreads();
    }

    // ---- write O ----
#pragma unroll
    for (int nt = 0; nt < 8; ++nt) {
        int col = nt * 8 + qq * 2;
        *reinterpret_cast<float2*>(Ob + (size_t)(row0 + g) * HD + col) =
            make_float2(o[nt][0], o[nt][1]);
        *reinterpret_cast<float2*>(Ob + (size_t)(row0 + g + 8) * HD + col) =
            make_float2(o[nt][2], o[nt][3]);
    }
}

extern "C" void kernel_launch(void* const* d_in, const int* in_sizes, int n_in,
                              void* d_out, int out_size) {
    const float* q = (const float*)d_in[0];
    const float* k = (const float*)d_in[1];
    const float* v = (const float*)d_in[2];
    (void)in_sizes; (void)n_in; (void)out_size;
    const int n4 = BHN * SEQ * HD / 4;
    convert_kernel<<<(2 * n4) / 256, 256>>>(k, v);
    dim3 grid(SEQ / BM, BHN);
    attn_kernel<<<grid, NTHREADS>>>(q, (float*)d_out);
}

// round 5
// speedup vs baseline: 2.3371x; 1.1638x over previous
#include <cuda_runtime.h>
#include <cuda_fp16.h>
#include <cstdint>

#define BHN 16
#define SEQ 4096
#define HD 64
#define BM 128
#define BN 64
#define NTHREADS 128
#define KPITCH 72   // smem row pitch in halves (144B rows -> conflict-free LDSM)
#define NT (SEQ / BN)

// fp16 scratch copies of K and V (converted once per launch)
__device__ __half2 Ksc[BHN * SEQ * HD / 2];
__device__ __half2 Vsc[BHN * SEQ * HD / 2];

__device__ __forceinline__ float ex2f(float x) {
    float y;
    asm("ex2.approx.f32 %0, %1;" : "=f"(y) : "f"(x));
    return y;
}

__device__ __forceinline__ uint32_t packh2(float a, float b) {
    __half2 t = __floats2half2_rn(a, b);
    return reinterpret_cast<uint32_t&>(t);
}

__device__ __forceinline__ void mma16816(float c[4], const uint32_t a[4],
                                         uint32_t b0, uint32_t b1) {
    asm volatile(
        "mma.sync.aligned.m16n8k16.row.col.f32.f16.f16.f32 "
        "{%0,%1,%2,%3},{%4,%5,%6,%7},{%8,%9},{%0,%1,%2,%3};"
        : "+f"(c[0]), "+f"(c[1]), "+f"(c[2]), "+f"(c[3])
        : "r"(a[0]), "r"(a[1]), "r"(a[2]), "r"(a[3]), "r"(b0), "r"(b1));
}

__device__ __forceinline__ void ldsm_x4(uint32_t& r0, uint32_t& r1, uint32_t& r2,
                                        uint32_t& r3, uint32_t addr) {
    asm volatile("ldmatrix.sync.aligned.m8n8.x4.shared.b16 {%0,%1,%2,%3},[%4];"
                 : "=r"(r0), "=r"(r1), "=r"(r2), "=r"(r3) : "r"(addr));
}

__device__ __forceinline__ void ldsm_x4_t(uint32_t& r0, uint32_t& r1, uint32_t& r2,
                                          uint32_t& r3, uint32_t addr) {
    asm volatile("ldmatrix.sync.aligned.m8n8.x4.trans.shared.b16 {%0,%1,%2,%3},[%4];"
                 : "=r"(r0), "=r"(r1), "=r"(r2), "=r"(r3) : "r"(addr));
}

__device__ __forceinline__ void cpasync16(uint32_t dst, const void* src) {
    asm volatile("cp.async.cg.shared.global [%0],[%1],16;" :: "r"(dst), "l"(src));
}
__device__ __forceinline__ void cp_commit() {
    asm volatile("cp.async.commit_group;");
}
template <int N>
__device__ __forceinline__ void cp_wait() {
    asm volatile("cp.async.wait_group %0;" :: "n"(N));
}

// prefetch one [BN x HD] fp16 tile into padded smem, rows PERMUTED within each
// 16-key group: storage row s holds actual key a = ((s&6)<<1)|((s&8)>>2)|(s&1).
// This makes each MMA thread's owned S-columns actual-contiguous (float4 stores).
__device__ __forceinline__ void prefetch_tile(uint32_t dstbase, const __half* src,
                                              int tid) {
#pragma unroll
    for (int t = 0; t < 4; ++t) {
        int i = tid + t * NTHREADS;
        int r = i >> 3;
        int c8 = (i & 7) << 3;
        int s = r & 15;
        int a = ((s & 6) << 1) | ((s & 8) >> 2) | (s & 1);
        int srcr = (r & 48) | a;
        cpasync16(dstbase + (uint32_t)((r * KPITCH + c8) * 2), src + srcr * HD + c8);
    }
}

// ---------------- pre-conversion kernel ----------------
__global__ void __launch_bounds__(256)
convert_kernel(const float* __restrict__ K, const float* __restrict__ V) {
    const int n4 = BHN * SEQ * HD / 4;
    int i = blockIdx.x * blockDim.x + threadIdx.x;
    if (i < n4) {
        float4 f = reinterpret_cast<const float4*>(K)[i];
        Ksc[2 * i] = __floats2half2_rn(f.x, f.y);
        Ksc[2 * i + 1] = __floats2half2_rn(f.z, f.w);
    } else {
        int j = i - n4;
        float4 f = reinterpret_cast<const float4*>(V)[j];
        Vsc[2 * j] = __floats2half2_rn(f.x, f.y);
        Vsc[2 * j + 1] = __floats2half2_rn(f.z, f.w);
    }
}

// ---------------- main attention kernel ----------------
__global__ void __launch_bounds__(NTHREADS, 2)
attn_kernel(const float* __restrict__ Qg, float* __restrict__ out) {
    __shared__ __half Kb[2][BN * KPITCH];
    __shared__ __half Vb[2][BN * KPITCH];

    const int bh = blockIdx.y;
    const float* Qb = Qg + (size_t)bh * SEQ * HD;
    const __half* Kb16 = reinterpret_cast<const __half*>(Ksc) + (size_t)bh * SEQ * HD;
    const __half* Vb16 = reinterpret_cast<const __half*>(Vsc) + (size_t)bh * SEQ * HD;
    float* Ob = out + (size_t)bh * SEQ * HD;
    float* Ab = out + (size_t)BHN * SEQ * HD + (size_t)bh * SEQ * SEQ;

    const int tid = threadIdx.x;
    const int warp = tid >> 5;
    const int lane = tid & 31;
    const int g = lane >> 2;
    const int qq = lane & 3;
    const int row0 = blockIdx.x * BM + warp * 32;   // 32 rows per warp

    const uint32_t bK0 = (uint32_t)__cvta_generic_to_shared(&Kb[0][0]);
    const uint32_t bK1 = (uint32_t)__cvta_generic_to_shared(&Kb[1][0]);
    const uint32_t bV0 = (uint32_t)__cvta_generic_to_shared(&Vb[0][0]);
    const uint32_t bV1 = (uint32_t)__cvta_generic_to_shared(&Vb[1][0]);

    // LDSM lane offsets
    const int qk_r = (lane & 7) + ((lane & 16) ? 8 : 0);
    const int qk_c = (lane & 8) ? 8 : 0;
    const uint32_t offK = (uint32_t)((qk_r * KPITCH + qk_c) * 2);
    const int v_r = (lane & 7) + ((lane & 8) ? 8 : 0);
    const int v_c = (lane & 16) ? 8 : 0;
    const uint32_t offV = (uint32_t)((v_r * KPITCH + v_c) * 2);
    const uint32_t NPOFF = 16 * KPITCH * 2;

    // ---- Q fragments fp16, two 16-row fragments per warp ----
    uint32_t qh[2][4][4];
#pragma unroll
    for (int rf = 0; rf < 2; ++rf)
#pragma unroll
        for (int kc = 0; kc < 4; ++kc)
#pragma unroll
            for (int p = 0; p < 4; ++p) {
                int r = row0 + rf * 16 + g + (p & 1) * 8;
                int d = kc * 16 + (p >> 1) * 8 + qq * 2;
                float2 f = *reinterpret_cast<const float2*>(Qb + (size_t)r * HD + d);
                qh[rf][kc][p] = packh2(f.x, f.y);
            }

    const float SC = 0.1803368801111244f;  // (1/sqrt(64)) * log2(e)

    // ================= PASS A: row sums =================
    float rs[2][2] = {};
    prefetch_tile(bK0, Kb16, tid);
    cp_commit();
    for (int kt = 0; kt < NT; ++kt) {
        if (kt + 1 < NT) {
            prefetch_tile((kt & 1) ? bK0 : bK1, Kb16 + (size_t)(kt + 1) * BN * HD, tid);
            cp_commit();
            cp_wait<1>();
        } else {
            cp_wait<0>();
        }
        __syncthreads();
        const uint32_t aK = ((kt & 1) ? bK1 : bK0) + offK;
        float c[2][8][4] = {};
#pragma unroll
        for (int kc = 0; kc < 4; ++kc) {
#pragma unroll
            for (int np = 0; np < 4; ++np) {
                uint32_t h0, h1, h2, h3;
                ldsm_x4(h0, h1, h2, h3, aK + np * NPOFF + kc * 32);
#pragma unroll
                for (int rf = 0; rf < 2; ++rf) {
                    mma16816(c[rf][2 * np], qh[rf][kc], h0, h1);
                    mma16816(c[rf][2 * np + 1], qh[rf][kc], h2, h3);
                }
            }
        }
#pragma unroll
        for (int rf = 0; rf < 2; ++rf)
#pragma unroll
            for (int nt = 0; nt < 8; ++nt) {
                rs[rf][0] += ex2f(c[rf][nt][0] * SC) + ex2f(c[rf][nt][1] * SC);
                rs[rf][1] += ex2f(c[rf][nt][2] * SC) + ex2f(c[rf][nt][3] * SC);
            }
        __syncthreads();
    }
    float inv[2][2];
#pragma unroll
    for (int rf = 0; rf < 2; ++rf)
#pragma unroll
        for (int h = 0; h < 2; ++h) {
            float v = rs[rf][h];
            v += __shfl_xor_sync(0xffffffffu, v, 1);
            v += __shfl_xor_sync(0xffffffffu, v, 2);
            inv[rf][h] = 1.f / v;
        }

    // ========== PASS B: S, write attention, accumulate O ==========
    float o[2][8][4] = {};
    prefetch_tile(bK0, Kb16, tid);
    prefetch_tile(bV0, Vb16, tid);
    cp_commit();
    for (int kt = 0; kt < NT; ++kt) {
        if (kt + 1 < NT) {
            const uint32_t dK = (kt & 1) ? bK0 : bK1;
            const uint32_t dV = (kt & 1) ? bV0 : bV1;
            prefetch_tile(dK, Kb16 + (size_t)(kt + 1) * BN * HD, tid);
            prefetch_tile(dV, Vb16 + (size_t)(kt + 1) * BN * HD, tid);
            cp_commit();
            cp_wait<1>();
        } else {
            cp_wait<0>();
        }
        __syncthreads();
        const uint32_t aK = ((kt & 1) ? bK1 : bK0) + offK;
        const uint32_t aV = ((kt & 1) ? bV1 : bV0) + offV;

        float c[2][8][4] = {};
#pragma unroll
        for (int kc = 0; kc < 4; ++kc) {
#pragma unroll
            for (int np = 0; np < 4; ++np) {
                uint32_t h0, h1, h2, h3;
                ldsm_x4(h0, h1, h2, h3, aK + np * NPOFF + kc * 32);
#pragma unroll
                for (int rf = 0; rf < 2; ++rf) {
                    mma16816(c[rf][2 * np], qh[rf][kc], h0, h1);
                    mma16816(c[rf][2 * np + 1], qh[rf][kc], h2, h3);
                }
            }
        }

        // exp + normalize + store attention as contiguous float4 (keys permuted)
#pragma unroll
        for (int rf = 0; rf < 2; ++rf) {
            const float i0 = inv[rf][0], i1 = inv[rf][1];
            float* arow0 = Ab + (size_t)(row0 + rf * 16 + g) * SEQ + kt * BN + qq * 4;
            float* arow1 = arow0 + 8 * SEQ;
#pragma unroll
            for (int P = 0; P < 4; ++P) {
                float* p0 = c[rf][2 * P];
                float* p1 = c[rf][2 * P + 1];
                p0[0] = ex2f(p0[0] * SC) * i0;
                p0[1] = ex2f(p0[1] * SC) * i0;
                p0[2] = ex2f(p0[2] * SC) * i1;
                p0[3] = ex2f(p0[3] * SC) * i1;
                p1[0] = ex2f(p1[0] * SC) * i0;
                p1[1] = ex2f(p1[1] * SC) * i0;
                p1[2] = ex2f(p1[2] * SC) * i1;
                p1[3] = ex2f(p1[3] * SC) * i1;
                // thread's actual columns: kt*64 + 16P + 4qq .. +3
                __stcs(reinterpret_cast<float4*>(arow0 + 16 * P),
                       make_float4(p0[0], p0[1], p1[0], p1[1]));
                __stcs(reinterpret_cast<float4*>(arow1 + 16 * P),
                       make_float4(p0[2], p0[3], p1[2], p1[3]));
            }
        }

        // AV: P (fp16, storage order) x V (fp16, rows in same storage order)
#pragma unroll
        for (int kcp = 0; kcp < 4; ++kcp) {
            const int t0 = 2 * kcp, t1 = 2 * kcp + 1;
            uint32_t ah[2][4];
#pragma unroll
            for (int rf = 0; rf < 2; ++rf) {
                ah[rf][0] = packh2(c[rf][t0][0], c[rf][t0][1]);
                ah[rf][1] = packh2(c[rf][t0][2], c[rf][t0][3]);
                ah[rf][2] = packh2(c[rf][t1][0], c[rf][t1][1]);
                ah[rf][3] = packh2(c[rf][t1][2], c[rf][t1][3]);
            }
#pragma unroll
            for (int np = 0; np < 4; ++np) {
                uint32_t v0, v1, v2, v3;
                ldsm_x4_t(v0, v1, v2, v3, aV + kcp * NPOFF + np * 32);
#pragma unroll
                for (int rf = 0; rf < 2; ++rf) {
                    mma16816(o[rf][2 * np], ah[rf], v0, v1);
                    mma16816(o[rf][2 * np + 1], ah[rf], v2, v3);
                }
            }
        }
        __syncthreads();
    }

    // ---- write O ----
#pragma unroll
    for (int rf = 0; rf < 2; ++rf)
#pragma unroll
        for (int nt = 0; nt < 8; ++nt) {
            int col = nt * 8 + qq * 2;
            int r = row0 + rf * 16 + g;
            *reinterpret_cast<float2*>(Ob + (size_t)r * HD + col) =
                make_float2(o[rf][nt][0], o[rf][nt][1]);
            *reinterpret_cast<float2*>(Ob + (size_t)(r + 8) * HD + col) =
                make_float2(o[rf][nt][2], o[rf][nt][3]);
        }
}

extern "C" void kernel_launch(void* const* d_in, const int* in_sizes, int n_in,
                              void* d_out, int out_size) {
    const float* q = (const float*)d_in[0];
    const float* k = (const float*)d_in[1];
    const float* v = (const float*)d_in[2];
    (void)in_sizes; (void)n_in; (void)out_size;
    const int n4 = BHN * SEQ * HD / 4;
    convert_kernel<<<(2 * n4) / 256, 256>>>(k, v);
    dim3 grid(SEQ / BM, BHN);
    attn_kernel<<<grid, NTHREADS>>>(q, (float*)d_out);
}